// round 7
// baseline (speedup 1.0000x reference)
#include <cuda_runtime.h>
#include <cuda_bf16.h>
#include <cstdint>
#include <cstddef>

// Problem constants
#define B_   2
#define S_   2048
#define D_   1024
#define H_   16
#define DH_  64
#define BS_  (B_ * S_)            // 4096
#define QKV_N (3 * D_)            // 3072
#define OUT_ATTN_ELEMS ((size_t)BS_ * D_)           // 4,194,304

// Scratch (allocation-free rule: __device__ globals)
__device__ float g_qkv[BS_ * QKV_N];   // [4096, 3072] : Q | K | V packed (fp32)
__device__ float g_attn[BS_ * D_];     // [4096, 1024] : pre-proj attn output
__device__ float g_mx[B_ * H_ * S_];   // per-row softmax max
__device__ float g_inv[B_ * H_ * S_];  // per-row 1/sum
// bf16 split operands for the dense GEMMs
__device__ __nv_bfloat16 g_ahi[BS_ * D_];
__device__ __nv_bfloat16 g_alo[BS_ * D_];
__device__ __nv_bfloat16 g_w1hi[QKV_N * D_];   // c_attn_w^T [3072,1024]
__device__ __nv_bfloat16 g_w1lo[QKV_N * D_];
__device__ __nv_bfloat16 g_w2hi[D_ * D_];      // c_proj_w^T [1024,1024]
__device__ __nv_bfloat16 g_w2lo[D_ * D_];

// ===========================================================================
// HMMA / async-copy helpers
// ===========================================================================
__device__ __forceinline__ uint32_t smem_u32(const void* p) {
    uint32_t a;
    asm("{ .reg .u64 t; cvta.to.shared.u64 t, %1; cvt.u32.u64 %0, t; }"
        : "=r"(a) : "l"(p));
    return a;
}

__device__ __forceinline__ void ldm_x4(uint32_t r[4], uint32_t saddr) {
    asm volatile("ldmatrix.sync.aligned.m8n8.x4.shared.b16 {%0,%1,%2,%3}, [%4];"
                 : "=r"(r[0]), "=r"(r[1]), "=r"(r[2]), "=r"(r[3]) : "r"(saddr));
}

__device__ __forceinline__ void mma_bf16(float c[4], const uint32_t a[4],
                                         const uint32_t b[2]) {
    asm volatile(
        "mma.sync.aligned.m16n8k16.row.col.f32.bf16.bf16.f32 "
        "{%0,%1,%2,%3}, {%4,%5,%6,%7}, {%8,%9}, {%0,%1,%2,%3};"
        : "+f"(c[0]), "+f"(c[1]), "+f"(c[2]), "+f"(c[3])
        : "r"(a[0]), "r"(a[1]), "r"(a[2]), "r"(a[3]), "r"(b[0]), "r"(b[1]));
}

__device__ __forceinline__ void cp16(uint32_t saddr, const void* gaddr) {
    asm volatile("cp.async.ca.shared.global [%0], [%1], 16;"
                 :: "r"(saddr), "l"(gaddr));
}
#define CP_COMMIT() asm volatile("cp.async.commit_group;" ::: "memory")
#define CP_WAIT(N)  asm volatile("cp.async.wait_group %0;" :: "n"(N) : "memory")

// Split a float4 into hi/lo bf16x4, store as 8B each.
__device__ __forceinline__ void split4(float4 v, __nv_bfloat16* hp,
                                       __nv_bfloat16* lp)
{
    __nv_bfloat162 h0, h1, l0, l1;
    h0.x = __float2bfloat16(v.x); h0.y = __float2bfloat16(v.y);
    h1.x = __float2bfloat16(v.z); h1.y = __float2bfloat16(v.w);
    l0.x = __float2bfloat16(v.x - __bfloat162float(h0.x));
    l0.y = __float2bfloat16(v.y - __bfloat162float(h0.y));
    l1.x = __float2bfloat16(v.z - __bfloat162float(h1.x));
    l1.y = __float2bfloat16(v.w - __bfloat162float(h1.y));
    uint2 hu, lu;
    hu.x = *reinterpret_cast<uint32_t*>(&h0);
    hu.y = *reinterpret_cast<uint32_t*>(&h1);
    lu.x = *reinterpret_cast<uint32_t*>(&l0);
    lu.y = *reinterpret_cast<uint32_t*>(&l1);
    *reinterpret_cast<uint2*>(hp) = hu;
    *reinterpret_cast<uint2*>(lp) = lu;
}

// ===========================================================================
// Split kernels: fp32 -> bf16 hi/lo (for dense GEMM operands)
// ===========================================================================
__global__ __launch_bounds__(256)
void split_rows_kernel(const float* __restrict__ in,
                       __nv_bfloat16* __restrict__ hi,
                       __nv_bfloat16* __restrict__ lo, int n4)
{
    int i = blockIdx.x * 256 + threadIdx.x;
    if (i >= n4) return;
    float4 v = reinterpret_cast<const float4*>(in)[i];
    split4(v, hi + i * 4, lo + i * 4);
}

__global__ __launch_bounds__(256)
void split_T_kernel(const float* __restrict__ in,
                    __nv_bfloat16* __restrict__ hi,
                    __nv_bfloat16* __restrict__ lo, int K, int N)
{
    __shared__ float t[32][33];
    int n0 = blockIdx.x * 32, k0 = blockIdx.y * 32;
    int tx = threadIdx.x & 31, ty = threadIdx.x >> 5;   // 32 x 8
#pragma unroll
    for (int i = 0; i < 4; i++)
        t[ty + 8 * i][tx] = in[(size_t)(k0 + ty + 8 * i) * N + n0 + tx];
    __syncthreads();
#pragma unroll
    for (int i = 0; i < 4; i++) {
        float v = t[tx][ty + 8 * i];
        __nv_bfloat16 h = __float2bfloat16(v);
        __nv_bfloat16 l = __float2bfloat16(v - __bfloat162float(h));
        size_t o = (size_t)(n0 + ty + 8 * i) * K + k0 + tx;
        hi[o] = h;
        lo[o] = l;
    }
}

// ===========================================================================
// cp.async double-buffered HMMA GEMM (pass-major MMA ordering)
// ===========================================================================
#define SPAD    40
#define TILE_E  (128 * SPAD)
#define STAGE_E (4 * TILE_E)
#define GEMM_SMEM_BYTES (2 * STAGE_E * 2)

__device__ __forceinline__ void gemm_issue_loads(
    const __nv_bfloat16* __restrict__ Ahi, const __nv_bfloat16* __restrict__ Alo,
    const __nv_bfloat16* __restrict__ Bhi, const __nv_bfloat16* __restrict__ Blo,
    uint32_t sm_base, int stage, int row0, int col0, int kk, int K, int tid)
{
    const uint32_t st = sm_base + (uint32_t)stage * STAGE_E * 2;
#pragma unroll
    for (int u = 0; u < 2; u++) {
        int s  = tid + u * 256;
        int r  = s >> 2;
        int cg = (s & 3) * 8;
        size_t goffA = (size_t)(row0 + r) * K + kk + cg;
        size_t goffB = (size_t)(col0 + r) * K + kk + cg;
        uint32_t so = (uint32_t)(r * SPAD + cg) * 2;
        cp16(st + 0 * TILE_E * 2 + so, Ahi + goffA);
        cp16(st + 1 * TILE_E * 2 + so, Alo + goffA);
        cp16(st + 2 * TILE_E * 2 + so, Bhi + goffB);
        cp16(st + 3 * TILE_E * 2 + so, Blo + goffB);
    }
}

__global__ __launch_bounds__(256, 2)
void gemm_hmma_async(const __nv_bfloat16* __restrict__ Ahi,
                     const __nv_bfloat16* __restrict__ Alo,
                     const __nv_bfloat16* __restrict__ Bhi,
                     const __nv_bfloat16* __restrict__ Blo,
                     const float* __restrict__ bias,
                     float* __restrict__ C, int M, int N, int K)
{
    extern __shared__ __nv_bfloat16 sm[];
    const uint32_t sm_base = smem_u32(sm);

    const int tid  = threadIdx.x;
    const int lane = tid & 31;
    const int warp = tid >> 5;
    const int row0 = blockIdx.y * 128;
    const int col0 = blockIdx.x * 128;
    const int warp_m = (warp & 3) * 32;
    const int warp_n = (warp >> 2) * 64;

    float acc[2][8][4];
#pragma unroll
    for (int i = 0; i < 2; i++)
#pragma unroll
        for (int j = 0; j < 8; j++)
#pragma unroll
            for (int r = 0; r < 4; r++) acc[i][j][r] = 0.0f;

    const int a_r = warp_m + (lane & 15);
    const int a_c = (lane >> 4) * 8;
    const int b_r = warp_n + (lane & 7) + (lane >> 4) * 8;
    const int b_c = ((lane >> 3) & 1) * 8;

    const int nch = K >> 5;

    gemm_issue_loads(Ahi, Alo, Bhi, Blo, sm_base, 0, row0, col0, 0, K, tid);
    CP_COMMIT();

    for (int c = 0; c < nch; c++) {
        const int cur = c & 1;
        if (c + 1 < nch) {
            gemm_issue_loads(Ahi, Alo, Bhi, Blo, sm_base, cur ^ 1,
                             row0, col0, (c + 1) << 5, K, tid);
            CP_COMMIT();
            CP_WAIT(1);
        } else {
            CP_WAIT(0);
        }
        __syncthreads();

        const __nv_bfloat16* sAhi = sm + cur * STAGE_E + 0 * TILE_E;
        const __nv_bfloat16* sAlo = sm + cur * STAGE_E + 1 * TILE_E;
        const __nv_bfloat16* sBhi = sm + cur * STAGE_E + 2 * TILE_E;
        const __nv_bfloat16* sBlo = sm + cur * STAGE_E + 3 * TILE_E;

#pragma unroll
        for (int ks = 0; ks < 32; ks += 16) {
            uint32_t a_h[2][4], a_l[2][4];
            uint32_t b_h[8][2], b_l[8][2];
#pragma unroll
            for (int i = 0; i < 2; i++) {
                int el = (a_r + i * 16) * SPAD + ks + a_c;
                ldm_x4(a_h[i], smem_u32(sAhi + el));
                ldm_x4(a_l[i], smem_u32(sAlo + el));
            }
#pragma unroll
            for (int jj = 0; jj < 4; jj++) {
                int el = (b_r + jj * 16) * SPAD + ks + b_c;
                ldm_x4(&b_h[jj * 2][0], smem_u32(sBhi + el));
                ldm_x4(&b_l[jj * 2][0], smem_u32(sBlo + el));
            }
#pragma unroll
            for (int i = 0; i < 2; i++)
#pragma unroll
                for (int j = 0; j < 8; j++)
                    mma_bf16(acc[i][j], a_h[i], b_h[j]);
#pragma unroll
            for (int i = 0; i < 2; i++)
#pragma unroll
                for (int j = 0; j < 8; j++)
                    mma_bf16(acc[i][j], a_h[i], b_l[j]);
#pragma unroll
            for (int i = 0; i < 2; i++)
#pragma unroll
                for (int j = 0; j < 8; j++)
                    mma_bf16(acc[i][j], a_l[i], b_h[j]);
        }
        __syncthreads();
    }

#pragma unroll
    for (int i = 0; i < 2; i++) {
#pragma unroll
        for (int j = 0; j < 8; j++) {
            int m = row0 + warp_m + i * 16 + (lane >> 2);
            int n = col0 + warp_n + j * 8 + (lane & 3) * 2;
            float2 bz = *reinterpret_cast<const float2*>(&bias[n]);
            float2 o0; o0.x = acc[i][j][0] + bz.x; o0.y = acc[i][j][1] + bz.y;
            float2 o1; o1.x = acc[i][j][2] + bz.x; o1.y = acc[i][j][3] + bz.y;
            *reinterpret_cast<float2*>(&C[(size_t)m * N + n]) = o0;
            *reinterpret_cast<float2*>(&C[(size_t)(m + 8) * N + n]) = o1;
        }
    }
}

// ===========================================================================
// P1: scores + per-row softmax stats.
// CTA = (qblk, bh). Q tile resident; iterate causal k-chunks; HMMA scores;
// store RAW scaled scores to W; online max/exp-sum per row -> g_mx/g_inv.
// ===========================================================================
#define QSPAD 72
#define P1_SMEM_BYTES (4 * 128 * QSPAD * 2)

__global__ __launch_bounds__(256)
void p1_scores_stats(float* __restrict__ W)
{
    extern __shared__ __nv_bfloat16 dsm[];
    __nv_bfloat16* sQh = dsm;
    __nv_bfloat16* sQl = sQh + 128 * QSPAD;
    __nv_bfloat16* sKh = sQl + 128 * QSPAD;
    __nv_bfloat16* sKl = sKh + 128 * QSPAD;
    __shared__ float sredA[2][128];
    __shared__ float sredB[2][128];

    const int tid  = threadIdx.x;
    const int lane = tid & 31;
    const int warp = tid >> 5;
    const int qblk = 15 - blockIdx.x;          // heavy blocks first
    const int bh   = blockIdx.y;
    const int b    = bh >> 4;
    const int h    = bh & 15;
    const int q0   = qblk * 128;

    const int warp_m = (warp & 3) * 32;
    const int warp_n = (warp >> 2) * 64;
    const int wn     = warp >> 2;

    const int a_r = warp_m + (lane & 15);
    const int a_c = (lane >> 4) * 8;
    const int b_r = warp_n + (lane & 7) + (lane >> 4) * 8;
    const int b_c = ((lane >> 3) & 1) * 8;

    const int lr  = tid >> 1;            // 0..127
    const int lc0 = (tid & 1) * 32;      // 0 or 32

    // load Q tile once (128 x 64), split to hi/lo
#pragma unroll
    for (int i = 0; i < 8; i++) {
        int c = lc0 + i * 4;
        float4 vq = *reinterpret_cast<const float4*>(
            &g_qkv[(size_t)(b * S_ + q0 + lr) * QKV_N + h * DH_ + c]);
        split4(vq, &sQh[lr * QSPAD + c], &sQl[lr * QSPAD + c]);
    }

    // per-thread running stats for its 4 rows: idx = i*2+hf,
    // row = warp_m + i*16 + hf*8 + (lane>>2)
    float m_run[4] = {-1e30f, -1e30f, -1e30f, -1e30f};
    float s_run[4] = {0.0f, 0.0f, 0.0f, 0.0f};

    float* Wbh = W + (size_t)bh * S_ * S_;

    for (int kt = 0; kt <= qblk; kt++) {
        const int k0 = kt * 128;
        __syncthreads();   // protect sK (and sQ on first iter)
#pragma unroll
        for (int i = 0; i < 8; i++) {
            int c = lc0 + i * 4;
            float4 vk = *reinterpret_cast<const float4*>(
                &g_qkv[(size_t)(b * S_ + k0 + lr) * QKV_N + D_ + h * DH_ + c]);
            split4(vk, &sKh[lr * QSPAD + c], &sKl[lr * QSPAD + c]);
        }
        __syncthreads();

        float acc[2][8][4];
#pragma unroll
        for (int i = 0; i < 2; i++)
#pragma unroll
            for (int j = 0; j < 8; j++)
#pragma unroll
                for (int r = 0; r < 4; r++) acc[i][j][r] = 0.0f;

#pragma unroll
        for (int ks = 0; ks < 64; ks += 16) {
            uint32_t a_h[2][4], a_l[2][4];
            uint32_t b_h[8][2], b_l[8][2];
#pragma unroll
            for (int i = 0; i < 2; i++) {
                int el = (a_r + i * 16) * QSPAD + ks + a_c;
                ldm_x4(a_h[i], smem_u32(sQh + el));
                ldm_x4(a_l[i], smem_u32(sQl + el));
            }
#pragma unroll
            for (int jj = 0; jj < 4; jj++) {
                int el = (b_r + jj * 16) * QSPAD + ks + b_c;
                ldm_x4(&b_h[jj * 2][0], smem_u32(sKh + el));
                ldm_x4(&b_l[jj * 2][0], smem_u32(sKl + el));
            }
#pragma unroll
            for (int i = 0; i < 2; i++)
#pragma unroll
                for (int j = 0; j < 8; j++)
                    mma_bf16(acc[i][j], a_h[i], b_h[j]);
#pragma unroll
            for (int i = 0; i < 2; i++)
#pragma unroll
                for (int j = 0; j < 8; j++)
                    mma_bf16(acc[i][j], a_h[i], b_l[j]);
#pragma unroll
            for (int i = 0; i < 2; i++)
#pragma unroll
                for (int j = 0; j < 8; j++)
                    mma_bf16(acc[i][j], a_l[i], b_h[j]);
        }

        // scale
#pragma unroll
        for (int i = 0; i < 2; i++)
#pragma unroll
            for (int j = 0; j < 8; j++)
#pragma unroll
                for (int r = 0; r < 4; r++) acc[i][j][r] *= 0.125f;

        const bool diag = (kt == qblk);

        // ---- per-row chunk max ----
        float vmax[4] = {-1e30f, -1e30f, -1e30f, -1e30f};
#pragma unroll
        for (int i = 0; i < 2; i++) {
            int qr = q0 + warp_m + i * 16 + (lane >> 2);
#pragma unroll
            for (int j = 0; j < 8; j++) {
                int kb = k0 + warp_n + j * 8 + (lane & 3) * 2;
                if (!diag || kb     <= qr)     vmax[i*2]   = fmaxf(vmax[i*2],   acc[i][j][0]);
                if (!diag || kb + 1 <= qr)     vmax[i*2]   = fmaxf(vmax[i*2],   acc[i][j][1]);
                if (!diag || kb     <= qr + 8) vmax[i*2+1] = fmaxf(vmax[i*2+1], acc[i][j][2]);
                if (!diag || kb + 1 <= qr + 8) vmax[i*2+1] = fmaxf(vmax[i*2+1], acc[i][j][3]);
            }
        }
#pragma unroll
        for (int idx = 0; idx < 4; idx++) {
            vmax[idx] = fmaxf(vmax[idx], __shfl_xor_sync(0xFFFFFFFFu, vmax[idx], 1));
            vmax[idx] = fmaxf(vmax[idx], __shfl_xor_sync(0xFFFFFFFFu, vmax[idx], 2));
        }
        if ((lane & 3) == 0) {
#pragma unroll
            for (int idx = 0; idx < 4; idx++) {
                int rowl = warp_m + (idx >> 1) * 16 + (idx & 1) * 8 + (lane >> 2);
                sredA[wn][rowl] = vmax[idx];
            }
        }
        __syncthreads();
        float m_c[4];
#pragma unroll
        for (int idx = 0; idx < 4; idx++) {
            int rowl = warp_m + (idx >> 1) * 16 + (idx & 1) * 8 + (lane >> 2);
            m_c[idx] = fmaxf(vmax[idx], sredA[wn ^ 1][rowl]);
        }

        // ---- per-row chunk exp-sum ----
        float ssum[4] = {0.0f, 0.0f, 0.0f, 0.0f};
#pragma unroll
        for (int i = 0; i < 2; i++) {
            int qr = q0 + warp_m + i * 16 + (lane >> 2);
#pragma unroll
            for (int j = 0; j < 8; j++) {
                int kb = k0 + warp_n + j * 8 + (lane & 3) * 2;
                if (!diag || kb     <= qr)     ssum[i*2]   += __expf(acc[i][j][0] - m_c[i*2]);
                if (!diag || kb + 1 <= qr)     ssum[i*2]   += __expf(acc[i][j][1] - m_c[i*2]);
                if (!diag || kb     <= qr + 8) ssum[i*2+1] += __expf(acc[i][j][2] - m_c[i*2+1]);
                if (!diag || kb + 1 <= qr + 8) ssum[i*2+1] += __expf(acc[i][j][3] - m_c[i*2+1]);
            }
        }
#pragma unroll
        for (int idx = 0; idx < 4; idx++) {
            ssum[idx] += __shfl_xor_sync(0xFFFFFFFFu, ssum[idx], 1);
            ssum[idx] += __shfl_xor_sync(0xFFFFFFFFu, ssum[idx], 2);
        }
        if ((lane & 3) == 0) {
#pragma unroll
            for (int idx = 0; idx < 4; idx++) {
                int rowl = warp_m + (idx >> 1) * 16 + (idx & 1) * 8 + (lane >> 2);
                sredB[wn][rowl] = ssum[idx];
            }
        }
        __syncthreads();
#pragma unroll
        for (int idx = 0; idx < 4; idx++) {
            int rowl = warp_m + (idx >> 1) * 16 + (idx & 1) * 8 + (lane >> 2);
            float s_c = ssum[idx] + sredB[wn ^ 1][rowl];
            float m_new = fmaxf(m_run[idx], m_c[idx]);
            s_run[idx] = s_run[idx] * __expf(m_run[idx] - m_new)
                       + s_c * __expf(m_c[idx] - m_new);
            m_run[idx] = m_new;
        }

        // ---- store raw scaled scores ----
#pragma unroll
        for (int i = 0; i < 2; i++) {
#pragma unroll
            for (int j = 0; j < 8; j++) {
                int q = q0 + warp_m + i * 16 + (lane >> 2);
                int k = k0 + warp_n + j * 8 + (lane & 3) * 2;
                float2 o0; o0.x = acc[i][j][0]; o0.y = acc[i][j][1];
                float2 o1; o1.x = acc[i][j][2]; o1.y = acc[i][j][3];
                *reinterpret_cast<float2*>(&Wbh[(size_t)q * S_ + k]) = o0;
                *reinterpret_cast<float2*>(&Wbh[(size_t)(q + 8) * S_ + k]) = o1;
            }
        }
    }

    if (wn == 0 && (lane & 3) == 0) {
#pragma unroll
        for (int idx = 0; idx < 4; idx++) {
            int rowg = q0 + warp_m + (idx >> 1) * 16 + (idx & 1) * 8 + (lane >> 2);
            g_mx[bh * S_ + rowg]  = m_run[idx];
            g_inv[bh * S_ + rowg] = 1.0f / s_run[idx];
        }
    }
}

// ===========================================================================
// P2: normalize weights (write final W incl. zero upper region) + AV HMMA.
// ===========================================================================
__global__ __launch_bounds__(256)
void p2_norm_av(float* __restrict__ W)
{
    __shared__ __nv_bfloat16 sW[2][128 * SPAD];
    __shared__ __nv_bfloat16 sV[2][64 * SPAD];

    const int tid  = threadIdx.x;
    const int lane = tid & 31;
    const int warp = tid >> 5;
    const int qblk = 15 - blockIdx.x;
    const int bh   = blockIdx.y;
    const int b    = bh >> 4;
    const int h    = bh & 15;
    const int q0   = qblk * 128;
    const int warp_m = warp * 16;

    float* Wbh = W + (size_t)bh * S_ * S_;
    const size_t vbase = (size_t)b * S_ * QKV_N + 2 * D_ + h * DH_;

    float acc[8][4];
#pragma unroll
    for (int j = 0; j < 8; j++)
#pragma unroll
        for (int r = 0; r < 4; r++) acc[j][r] = 0.0f;

    const int a_r = warp_m + (lane & 15);
    const int a_c = (lane >> 4) * 8;
    const int b_r = (lane & 7) + (lane >> 4) * 8;
    const int b_c = ((lane >> 3) & 1) * 8;

    const int wr  = tid >> 1;
    const int wc0 = (tid & 1) * 16;
    const int vd  = tid & 63;
    const int vk0 = (tid >> 6) * 8;

    const int qg = q0 + wr;
    const float mx_r  = g_mx[bh * S_ + qg];
    const float inv_r = g_inv[bh * S_ + qg];

    const int nch = (qblk + 1) * 4;
    for (int t = 0; t < nch; t++) {
        const int kc = t * 32;
        // load raw scores, normalize, write back, split into sW
#pragma unroll
        for (int i = 0; i < 4; i++) {
            int c = wc0 + i * 4;
            int kg = kc + c;
            float4 v = *reinterpret_cast<const float4*>(
                &Wbh[(size_t)qg * S_ + kg]);
            v.x = (kg     <= qg) ? __expf(v.x - mx_r) * inv_r : 0.0f;
            v.y = (kg + 1 <= qg) ? __expf(v.y - mx_r) * inv_r : 0.0f;
            v.z = (kg + 2 <= qg) ? __expf(v.z - mx_r) * inv_r : 0.0f;
            v.w = (kg + 3 <= qg) ? __expf(v.w - mx_r) * inv_r : 0.0f;
            *reinterpret_cast<float4*>(&Wbh[(size_t)qg * S_ + kg]) = v;
            split4(v, &sW[0][wr * SPAD + c], &sW[1][wr * SPAD + c]);
        }
        // load + split + transpose V tile [32 x 64] -> sV [d][k]
        {
            uint32_t hp[4], lp[4];
#pragma unroll
            for (int i = 0; i < 4; i++) {
                float x0 = g_qkv[vbase + (size_t)(kc + vk0 + 2 * i) * QKV_N + vd];
                float x1 = g_qkv[vbase + (size_t)(kc + vk0 + 2 * i + 1) * QKV_N + vd];
                __nv_bfloat162 hh, ll;
                hh.x = __float2bfloat16(x0); hh.y = __float2bfloat16(x1);
                ll.x = __float2bfloat16(x0 - __bfloat162float(hh.x));
                ll.y = __float2bfloat16(x1 - __bfloat162float(hh.y));
                hp[i] = *reinterpret_cast<uint32_t*>(&hh);
                lp[i] = *reinterpret_cast<uint32_t*>(&ll);
            }
            uint4 hv; hv.x = hp[0]; hv.y = hp[1]; hv.z = hp[2]; hv.w = hp[3];
            uint4 lv; lv.x = lp[0]; lv.y = lp[1]; lv.z = lp[2]; lv.w = lp[3];
            *reinterpret_cast<uint4*>(&sV[0][vd * SPAD + vk0]) = hv;
            *reinterpret_cast<uint4*>(&sV[1][vd * SPAD + vk0]) = lv;
        }
        __syncthreads();

#pragma unroll
        for (int ks = 0; ks < 32; ks += 16) {
            uint32_t a_h[4], a_l[4];
            uint32_t b_h[8][2], b_l[8][2];
            {
                int el = a_r * SPAD + ks + a_c;
                ldm_x4(a_h, smem_u32(&sW[0][el]));
                ldm_x4(a_l, smem_u32(&sW[1][el]));
            }
#pragma unroll
            for (int jj = 0; jj < 4; jj++) {
                int el = (b_r + jj * 16) * SPAD + ks + b_c;
                ldm_x4(&b_h[jj * 2][0], smem_u32(&sV[0][el]));
                ldm_x4(&b_l[jj * 2][0], smem_u32(&sV[1][el]));
            }
#pragma unroll
            for (int j = 0; j < 8; j++)
                mma_bf16(acc[j], a_h, b_h[j]);
#pragma unroll
            for (int j = 0; j < 8; j++)
                mma_bf16(acc[j], a_h, b_l[j]);
#pragma unroll
            for (int j = 0; j < 8; j++)
                mma_bf16(acc[j], a_l, b_h[j]);
        }
        __syncthreads();
    }

    // zero the untouched upper region of this q-block's rows
    {
        const int c0 = (qblk + 1) * 128;
        const int f4_per_row = (S_ - c0) >> 2;
        const int total = 128 * f4_per_row;
        float4 z; z.x = 0.0f; z.y = 0.0f; z.z = 0.0f; z.w = 0.0f;
        for (int idx = tid; idx < total; idx += 256) {
            int r  = idx / f4_per_row;
            int cc = c0 + (idx - r * f4_per_row) * 4;
            *reinterpret_cast<float4*>(&Wbh[(size_t)(q0 + r) * S_ + cc]) = z;
        }
    }

    // epilogue: write g_attn rows
#pragma unroll
    for (int j = 0; j < 8; j++) {
        int m = q0 + warp_m + (lane >> 2);
        int n = j * 8 + (lane & 3) * 2;
        float2 o0; o0.x = acc[j][0]; o0.y = acc[j][1];
        float2 o1; o1.x = acc[j][2]; o1.y = acc[j][3];
        *reinterpret_cast<float2*>(
            &g_attn[(size_t)(b * S_ + m) * D_ + h * DH_ + n]) = o0;
        *reinterpret_cast<float2*>(
            &g_attn[(size_t)(b * S_ + m + 8) * D_ + h * DH_ + n]) = o1;
    }
}

// ---------------------------------------------------------------------------
extern "C" void kernel_launch(void* const* d_in, const int* in_sizes, int n_in,
                              void* d_out, int out_size)
{
    const float* hs       = (const float*)d_in[0];
    const float* c_attn_w = (const float*)d_in[1];
    const float* c_attn_b = (const float*)d_in[2];
    const float* c_proj_w = (const float*)d_in[3];
    const float* c_proj_b = (const float*)d_in[4];

    float* out  = (float*)d_out;
    float* Wout = out + OUT_ATTN_ELEMS;

    float *qkv_ptr = nullptr, *attn_ptr = nullptr;
    __nv_bfloat16 *ahi, *alo, *w1hi, *w1lo, *w2hi, *w2lo;
    cudaGetSymbolAddress((void**)&qkv_ptr, g_qkv);
    cudaGetSymbolAddress((void**)&attn_ptr, g_attn);
    cudaGetSymbolAddress((void**)&ahi,  g_ahi);
    cudaGetSymbolAddress((void**)&alo,  g_alo);
    cudaGetSymbolAddress((void**)&w1hi, g_w1hi);
    cudaGetSymbolAddress((void**)&w1lo, g_w1lo);
    cudaGetSymbolAddress((void**)&w2hi, g_w2hi);
    cudaGetSymbolAddress((void**)&w2lo, g_w2lo);

    static bool attr_set = false;
    if (!attr_set) {
        cudaFuncSetAttribute(gemm_hmma_async,
                             cudaFuncAttributeMaxDynamicSharedMemorySize,
                             GEMM_SMEM_BYTES);
        cudaFuncSetAttribute(p1_scores_stats,
                             cudaFuncAttributeMaxDynamicSharedMemorySize,
                             P1_SMEM_BYTES);
        attr_set = true;
    }

    // 0) splits for dense GEMMs
    split_rows_kernel<<<(BS_ * D_ / 4 + 255) / 256, 256>>>(hs, ahi, alo, BS_ * D_ / 4);
    split_T_kernel<<<dim3(QKV_N / 32, D_ / 32), 256>>>(c_attn_w, w1hi, w1lo, D_, QKV_N);
    split_T_kernel<<<dim3(D_ / 32, D_ / 32), 256>>>(c_proj_w, w2hi, w2lo, D_, D_);

    // 1) QKV GEMM (HMMA, cp.async pipelined)
    gemm_hmma_async<<<dim3(QKV_N / 128, BS_ / 128), 256, GEMM_SMEM_BYTES>>>(
        ahi, alo, w1hi, w1lo, c_attn_b, qkv_ptr, BS_, QKV_N, D_);

    // 2) P1: scores + stats (raw W + g_mx/g_inv)
    p1_scores_stats<<<dim3(16, B_ * H_), 256, P1_SMEM_BYTES>>>(Wout);

    // 3) P2: normalize + final W write + AV
    p2_norm_av<<<dim3(16, B_ * H_), 256>>>(Wout);

    // 4) split attn output, then proj GEMM
    split_rows_kernel<<<(BS_ * D_ / 4 + 255) / 256, 256>>>(attn_ptr, ahi, alo, BS_ * D_ / 4);
    gemm_hmma_async<<<dim3(D_ / 128, BS_ / 128), 256, GEMM_SMEM_BYTES>>>(
        ahi, alo, w2hi, w2lo, c_proj_b, out, BS_, D_, D_);
}

// round 8
// speedup vs baseline: 1.1276x; 1.1276x over previous
#include <cuda_runtime.h>
#include <cuda_bf16.h>
#include <cstdint>
#include <cstddef>

// Problem constants
#define B_   2
#define S_   2048
#define D_   1024
#define H_   16
#define DH_  64
#define BS_  (B_ * S_)            // 4096
#define QKV_N (3 * D_)            // 3072
#define OUT_ATTN_ELEMS ((size_t)BS_ * D_)           // 4,194,304
#define MASKED_BIAS -10000.0f

// Scratch (allocation-free rule: __device__ globals)
__device__ float g_qkv[BS_ * QKV_N];   // [4096, 3072] : Q | K | V packed (fp32)
// bf16 split operands for the dense GEMMs
__device__ __nv_bfloat16 g_ahi[BS_ * D_];
__device__ __nv_bfloat16 g_alo[BS_ * D_];
__device__ __nv_bfloat16 g_w1hi[QKV_N * D_];   // c_attn_w^T [3072,1024]
__device__ __nv_bfloat16 g_w1lo[QKV_N * D_];
__device__ __nv_bfloat16 g_w2hi[D_ * D_];      // c_proj_w^T [1024,1024]
__device__ __nv_bfloat16 g_w2lo[D_ * D_];

// ===========================================================================
// HMMA / async-copy helpers
// ===========================================================================
__device__ __forceinline__ uint32_t smem_u32(const void* p) {
    uint32_t a;
    asm("{ .reg .u64 t; cvta.to.shared.u64 t, %1; cvt.u32.u64 %0, t; }"
        : "=r"(a) : "l"(p));
    return a;
}

__device__ __forceinline__ void ldm_x4(uint32_t r[4], uint32_t saddr) {
    asm volatile("ldmatrix.sync.aligned.m8n8.x4.shared.b16 {%0,%1,%2,%3}, [%4];"
                 : "=r"(r[0]), "=r"(r[1]), "=r"(r[2]), "=r"(r[3]) : "r"(saddr));
}

__device__ __forceinline__ void mma_bf16(float c[4], const uint32_t a[4],
                                         const uint32_t b[2]) {
    asm volatile(
        "mma.sync.aligned.m16n8k16.row.col.f32.bf16.bf16.f32 "
        "{%0,%1,%2,%3}, {%4,%5,%6,%7}, {%8,%9}, {%0,%1,%2,%3};"
        : "+f"(c[0]), "+f"(c[1]), "+f"(c[2]), "+f"(c[3])
        : "r"(a[0]), "r"(a[1]), "r"(a[2]), "r"(a[3]), "r"(b[0]), "r"(b[1]));
}

__device__ __forceinline__ void cp16(uint32_t saddr, const void* gaddr) {
    asm volatile("cp.async.ca.shared.global [%0], [%1], 16;"
                 :: "r"(saddr), "l"(gaddr));
}
#define CP_COMMIT() asm volatile("cp.async.commit_group;" ::: "memory")
#define CP_WAIT(N)  asm volatile("cp.async.wait_group %0;" :: "n"(N) : "memory")

// Split a float4 into hi/lo bf16x4, store as 8B each.
__device__ __forceinline__ void split4(float4 v, __nv_bfloat16* hp,
                                       __nv_bfloat16* lp)
{
    __nv_bfloat162 h0, h1, l0, l1;
    h0.x = __float2bfloat16(v.x); h0.y = __float2bfloat16(v.y);
    h1.x = __float2bfloat16(v.z); h1.y = __float2bfloat16(v.w);
    l0.x = __float2bfloat16(v.x - __bfloat162float(h0.x));
    l0.y = __float2bfloat16(v.y - __bfloat162float(h0.y));
    l1.x = __float2bfloat16(v.z - __bfloat162float(h1.x));
    l1.y = __float2bfloat16(v.w - __bfloat162float(h1.y));
    uint2 hu, lu;
    hu.x = *reinterpret_cast<uint32_t*>(&h0);
    hu.y = *reinterpret_cast<uint32_t*>(&h1);
    lu.x = *reinterpret_cast<uint32_t*>(&l0);
    lu.y = *reinterpret_cast<uint32_t*>(&l1);
    *reinterpret_cast<uint2*>(hp) = hu;
    *reinterpret_cast<uint2*>(lp) = lu;
}

// ===========================================================================
// Split kernels: fp32 -> bf16 hi/lo (for dense GEMM operands)
// ===========================================================================
__global__ __launch_bounds__(256)
void split_rows_kernel(const float* __restrict__ in,
                       __nv_bfloat16* __restrict__ hi,
                       __nv_bfloat16* __restrict__ lo, int n4)
{
    int i = blockIdx.x * 256 + threadIdx.x;
    if (i >= n4) return;
    float4 v = reinterpret_cast<const float4*>(in)[i];
    split4(v, hi + i * 4, lo + i * 4);
}

__global__ __launch_bounds__(256)
void split_T_kernel(const float* __restrict__ in,
                    __nv_bfloat16* __restrict__ hi,
                    __nv_bfloat16* __restrict__ lo, int K, int N)
{
    __shared__ float t[32][33];
    int n0 = blockIdx.x * 32, k0 = blockIdx.y * 32;
    int tx = threadIdx.x & 31, ty = threadIdx.x >> 5;   // 32 x 8
#pragma unroll
    for (int i = 0; i < 4; i++)
        t[ty + 8 * i][tx] = in[(size_t)(k0 + ty + 8 * i) * N + n0 + tx];
    __syncthreads();
#pragma unroll
    for (int i = 0; i < 4; i++) {
        float v = t[tx][ty + 8 * i];
        __nv_bfloat16 h = __float2bfloat16(v);
        __nv_bfloat16 l = __float2bfloat16(v - __bfloat162float(h));
        size_t o = (size_t)(n0 + ty + 8 * i) * K + k0 + tx;
        hi[o] = h;
        lo[o] = l;
    }
}

// ===========================================================================
// cp.async double-buffered HMMA GEMM (pass-major MMA ordering)
// ===========================================================================
#define SPAD    40
#define TILE_E  (128 * SPAD)
#define STAGE_E (4 * TILE_E)
#define GEMM_SMEM_BYTES (2 * STAGE_E * 2)

__device__ __forceinline__ void gemm_issue_loads(
    const __nv_bfloat16* __restrict__ Ahi, const __nv_bfloat16* __restrict__ Alo,
    const __nv_bfloat16* __restrict__ Bhi, const __nv_bfloat16* __restrict__ Blo,
    uint32_t sm_base, int stage, int row0, int col0, int kk, int K, int tid)
{
    const uint32_t st = sm_base + (uint32_t)stage * STAGE_E * 2;
#pragma unroll
    for (int u = 0; u < 2; u++) {
        int s  = tid + u * 256;
        int r  = s >> 2;
        int cg = (s & 3) * 8;
        size_t goffA = (size_t)(row0 + r) * K + kk + cg;
        size_t goffB = (size_t)(col0 + r) * K + kk + cg;
        uint32_t so = (uint32_t)(r * SPAD + cg) * 2;
        cp16(st + 0 * TILE_E * 2 + so, Ahi + goffA);
        cp16(st + 1 * TILE_E * 2 + so, Alo + goffA);
        cp16(st + 2 * TILE_E * 2 + so, Bhi + goffB);
        cp16(st + 3 * TILE_E * 2 + so, Blo + goffB);
    }
}

__global__ __launch_bounds__(256, 2)
void gemm_hmma_async(const __nv_bfloat16* __restrict__ Ahi,
                     const __nv_bfloat16* __restrict__ Alo,
                     const __nv_bfloat16* __restrict__ Bhi,
                     const __nv_bfloat16* __restrict__ Blo,
                     const float* __restrict__ bias,
                     float* __restrict__ C, int M, int N, int K)
{
    extern __shared__ __nv_bfloat16 sm[];
    const uint32_t sm_base = smem_u32(sm);

    const int tid  = threadIdx.x;
    const int lane = tid & 31;
    const int warp = tid >> 5;
    const int row0 = blockIdx.y * 128;
    const int col0 = blockIdx.x * 128;
    const int warp_m = (warp & 3) * 32;
    const int warp_n = (warp >> 2) * 64;

    float acc[2][8][4];
#pragma unroll
    for (int i = 0; i < 2; i++)
#pragma unroll
        for (int j = 0; j < 8; j++)
#pragma unroll
            for (int r = 0; r < 4; r++) acc[i][j][r] = 0.0f;

    const int a_r = warp_m + (lane & 15);
    const int a_c = (lane >> 4) * 8;
    const int b_r = warp_n + (lane & 7) + (lane >> 4) * 8;
    const int b_c = ((lane >> 3) & 1) * 8;

    const int nch = K >> 5;

    gemm_issue_loads(Ahi, Alo, Bhi, Blo, sm_base, 0, row0, col0, 0, K, tid);
    CP_COMMIT();

    for (int c = 0; c < nch; c++) {
        const int cur = c & 1;
        if (c + 1 < nch) {
            gemm_issue_loads(Ahi, Alo, Bhi, Blo, sm_base, cur ^ 1,
                             row0, col0, (c + 1) << 5, K, tid);
            CP_COMMIT();
            CP_WAIT(1);
        } else {
            CP_WAIT(0);
        }
        __syncthreads();

        const __nv_bfloat16* sAhi = sm + cur * STAGE_E + 0 * TILE_E;
        const __nv_bfloat16* sAlo = sm + cur * STAGE_E + 1 * TILE_E;
        const __nv_bfloat16* sBhi = sm + cur * STAGE_E + 2 * TILE_E;
        const __nv_bfloat16* sBlo = sm + cur * STAGE_E + 3 * TILE_E;

#pragma unroll
        for (int ks = 0; ks < 32; ks += 16) {
            uint32_t a_h[2][4], a_l[2][4];
            uint32_t b_h[8][2], b_l[8][2];
#pragma unroll
            for (int i = 0; i < 2; i++) {
                int el = (a_r + i * 16) * SPAD + ks + a_c;
                ldm_x4(a_h[i], smem_u32(sAhi + el));
                ldm_x4(a_l[i], smem_u32(sAlo + el));
            }
#pragma unroll
            for (int jj = 0; jj < 4; jj++) {
                int el = (b_r + jj * 16) * SPAD + ks + b_c;
                ldm_x4(&b_h[jj * 2][0], smem_u32(sBhi + el));
                ldm_x4(&b_l[jj * 2][0], smem_u32(sBlo + el));
            }
#pragma unroll
            for (int i = 0; i < 2; i++)
#pragma unroll
                for (int j = 0; j < 8; j++)
                    mma_bf16(acc[i][j], a_h[i], b_h[j]);
#pragma unroll
            for (int i = 0; i < 2; i++)
#pragma unroll
                for (int j = 0; j < 8; j++)
                    mma_bf16(acc[i][j], a_h[i], b_l[j]);
#pragma unroll
            for (int i = 0; i < 2; i++)
#pragma unroll
                for (int j = 0; j < 8; j++)
                    mma_bf16(acc[i][j], a_l[i], b_h[j]);
        }
        __syncthreads();
    }

#pragma unroll
    for (int i = 0; i < 2; i++) {
#pragma unroll
        for (int j = 0; j < 8; j++) {
            int m = row0 + warp_m + i * 16 + (lane >> 2);
            int n = col0 + warp_n + j * 8 + (lane & 3) * 2;
            float2 bz = *reinterpret_cast<const float2*>(&bias[n]);
            float2 o0; o0.x = acc[i][j][0] + bz.x; o0.y = acc[i][j][1] + bz.y;
            float2 o1; o1.x = acc[i][j][2] + bz.x; o1.y = acc[i][j][3] + bz.y;
            *reinterpret_cast<float2*>(&C[(size_t)m * N + n]) = o0;
            *reinterpret_cast<float2*>(&C[(size_t)(m + 8) * N + n]) = o1;
        }
    }
}

// ===========================================================================
// Scores on HMMA: W[bh,q,k] = (Q.K)/8, masked. Lower-triangle tiles only.
// ===========================================================================
__global__ __launch_bounds__(256)
void scores_hmma_kernel(float* __restrict__ W)
{
    __shared__ __nv_bfloat16 sQ[2][128 * SPAD];
    __shared__ __nv_bfloat16 sK[2][128 * SPAD];

    const int tid  = threadIdx.x;
    const int lane = tid & 31;
    const int warp = tid >> 5;
    const int bh   = blockIdx.y;
    const int b    = bh >> 4;
    const int h    = bh & 15;

    int pair = blockIdx.x;
    int qt = (int)((-1.0f + sqrtf(1.0f + 8.0f * (float)pair)) * 0.5f);
    while ((qt + 1) * (qt + 2) / 2 <= pair) ++qt;
    while (qt * (qt + 1) / 2 > pair) --qt;
    const int kt = pair - qt * (qt + 1) / 2;

    const int q0 = qt * 128;
    const int k0 = kt * 128;
    const int warp_m = (warp & 3) * 32;
    const int warp_n = (warp >> 2) * 64;

    float acc[2][8][4];
#pragma unroll
    for (int i = 0; i < 2; i++)
#pragma unroll
        for (int j = 0; j < 8; j++)
#pragma unroll
            for (int r = 0; r < 4; r++) acc[i][j][r] = 0.0f;

    const int a_r = warp_m + (lane & 15);
    const int a_c = (lane >> 4) * 8;
    const int b_r = warp_n + (lane & 7) + (lane >> 4) * 8;
    const int b_c = ((lane >> 3) & 1) * 8;

    const size_t qbase = (size_t)(b * S_ + q0) * QKV_N + h * DH_;
    const size_t kbase = (size_t)(b * S_ + k0) * QKV_N + D_ + h * DH_;

    const int lr = tid >> 1;
    const int lc0 = (tid & 1) * 16;

    for (int dc = 0; dc < DH_; dc += 32) {
#pragma unroll
        for (int i = 0; i < 4; i++) {
            int c = lc0 + i * 4;
            float4 vq = *reinterpret_cast<const float4*>(
                &g_qkv[qbase + (size_t)lr * QKV_N + dc + c]);
            float4 vk = *reinterpret_cast<const float4*>(
                &g_qkv[kbase + (size_t)lr * QKV_N + dc + c]);
            split4(vq, &sQ[0][lr * SPAD + c], &sQ[1][lr * SPAD + c]);
            split4(vk, &sK[0][lr * SPAD + c], &sK[1][lr * SPAD + c]);
        }
        __syncthreads();

#pragma unroll
        for (int ks = 0; ks < 32; ks += 16) {
            uint32_t a_h[2][4], a_l[2][4];
            uint32_t b_h[8][2], b_l[8][2];
#pragma unroll
            for (int i = 0; i < 2; i++) {
                int el = (a_r + i * 16) * SPAD + ks + a_c;
                ldm_x4(a_h[i], smem_u32(&sQ[0][el]));
                ldm_x4(a_l[i], smem_u32(&sQ[1][el]));
            }
#pragma unroll
            for (int jj = 0; jj < 4; jj++) {
                int el = (b_r + jj * 16) * SPAD + ks + b_c;
                ldm_x4(&b_h[jj * 2][0], smem_u32(&sK[0][el]));
                ldm_x4(&b_l[jj * 2][0], smem_u32(&sK[1][el]));
            }
#pragma unroll
            for (int i = 0; i < 2; i++)
#pragma unroll
                for (int j = 0; j < 8; j++)
                    mma_bf16(acc[i][j], a_h[i], b_h[j]);
#pragma unroll
            for (int i = 0; i < 2; i++)
#pragma unroll
                for (int j = 0; j < 8; j++)
                    mma_bf16(acc[i][j], a_h[i], b_l[j]);
#pragma unroll
            for (int i = 0; i < 2; i++)
#pragma unroll
                for (int j = 0; j < 8; j++)
                    mma_bf16(acc[i][j], a_l[i], b_h[j]);
        }
        __syncthreads();
    }

    float* Wbh = W + (size_t)bh * S_ * S_;
#pragma unroll
    for (int i = 0; i < 2; i++) {
#pragma unroll
        for (int j = 0; j < 8; j++) {
            int q  = q0 + warp_m + i * 16 + (lane >> 2);
            int k  = k0 + warp_n + j * 8 + (lane & 3) * 2;
            float2 o0, o1;
            o0.x = (k     > q) ? MASKED_BIAS : acc[i][j][0] * 0.125f;
            o0.y = (k + 1 > q) ? MASKED_BIAS : acc[i][j][1] * 0.125f;
            o1.x = (k     > q + 8) ? MASKED_BIAS : acc[i][j][2] * 0.125f;
            o1.y = (k + 1 > q + 8) ? MASKED_BIAS : acc[i][j][3] * 0.125f;
            *reinterpret_cast<float2*>(&Wbh[(size_t)q * S_ + k]) = o0;
            *reinterpret_cast<float2*>(&Wbh[(size_t)(q + 8) * S_ + k]) = o1;
        }
    }
}

// ---------------------------------------------------------------------------
// Softmax in place: float4 IO, warp-shuffle reductions, __expf.
// Masked-region float4 loads are SKIPPED (never read garbage / upper tiles).
// ---------------------------------------------------------------------------
__global__ __launch_bounds__(256)
void softmax_kernel(float* __restrict__ W)
{
    const int tid = threadIdx.x;
    const int lane = tid & 31;
    const int warp = tid >> 5;
    const int row = blockIdx.x;
    const int q = row & (S_ - 1);
    const int nvalid = q + 1;
    float* w = W + (size_t)row * S_;

    __shared__ float red[8];

    float4 v[2];
    float m = -1e30f;
#pragma unroll
    for (int r = 0; r < 2; r++) {
        int k0 = (r * 256 + tid) * 4;
        float4 x;
        if (k0 < nvalid) {
            x = *reinterpret_cast<const float4*>(w + k0);
            x.x = (k0 + 0 < nvalid) ? x.x : -1e30f;
            x.y = (k0 + 1 < nvalid) ? x.y : -1e30f;
            x.z = (k0 + 2 < nvalid) ? x.z : -1e30f;
            x.w = (k0 + 3 < nvalid) ? x.w : -1e30f;
        } else {
            x.x = x.y = x.z = x.w = -1e30f;
        }
        v[r] = x;
        m = fmaxf(m, fmaxf(fmaxf(x.x, x.y), fmaxf(x.z, x.w)));
    }
#pragma unroll
    for (int off = 16; off > 0; off >>= 1)
        m = fmaxf(m, __shfl_xor_sync(0xFFFFFFFFu, m, off));
    if (lane == 0) red[warp] = m;
    __syncthreads();
    float mx = red[0];
#pragma unroll
    for (int i = 1; i < 8; i++) mx = fmaxf(mx, red[i]);
    __syncthreads();

    float s = 0.0f;
#pragma unroll
    for (int r = 0; r < 2; r++) {
        int k0 = (r * 256 + tid) * 4;
        float4 x = v[r];
        x.x = (k0 + 0 < nvalid) ? __expf(x.x - mx) : 0.0f;
        x.y = (k0 + 1 < nvalid) ? __expf(x.y - mx) : 0.0f;
        x.z = (k0 + 2 < nvalid) ? __expf(x.z - mx) : 0.0f;
        x.w = (k0 + 3 < nvalid) ? __expf(x.w - mx) : 0.0f;
        v[r] = x;
        s += x.x + x.y + x.z + x.w;
    }
#pragma unroll
    for (int off = 16; off > 0; off >>= 1)
        s += __shfl_xor_sync(0xFFFFFFFFu, s, off);
    if (lane == 0) red[warp] = s;
    __syncthreads();
    float tot = red[0];
#pragma unroll
    for (int i = 1; i < 8; i++) tot += red[i];
    const float inv = 1.0f / tot;

#pragma unroll
    for (int r = 0; r < 2; r++) {
        int k0 = (r * 256 + tid) * 4;
        float4 x = v[r];
        x.x *= inv; x.y *= inv; x.z *= inv; x.w *= inv;
        *reinterpret_cast<float4*>(w + k0) = x;
    }
}

// ===========================================================================
// AV on HMMA: attn = softmax(W) @ V, causal chunk range.
// Epilogue writes bf16 hi/lo directly into g_ahi/g_alo (merged-head layout)
// — no fp32 intermediate, no separate split pass.
// ===========================================================================
__global__ __launch_bounds__(256)
void av_hmma_kernel(const float* __restrict__ W)
{
    __shared__ __nv_bfloat16 sW[2][128 * SPAD];
    __shared__ __nv_bfloat16 sV[2][64 * SPAD];

    const int tid  = threadIdx.x;
    const int lane = tid & 31;
    const int warp = tid >> 5;
    const int bh   = blockIdx.y;
    const int b    = bh >> 4;
    const int h    = bh & 15;
    const int q0   = blockIdx.x * 128;
    const int warp_m = warp * 16;

    const float* Wbh = W + (size_t)bh * S_ * S_;
    const size_t vbase = (size_t)b * S_ * QKV_N + 2 * D_ + h * DH_;

    float acc[8][4];
#pragma unroll
    for (int j = 0; j < 8; j++)
#pragma unroll
        for (int r = 0; r < 4; r++) acc[j][r] = 0.0f;

    const int a_r = warp_m + (lane & 15);
    const int a_c = (lane >> 4) * 8;
    const int b_r = (lane & 7) + (lane >> 4) * 8;
    const int b_c = ((lane >> 3) & 1) * 8;

    const int wr  = tid >> 1;
    const int wc0 = (tid & 1) * 16;
    const int vd  = tid & 63;
    const int vk0 = (tid >> 6) * 8;

    const int nch = (blockIdx.x + 1) * 4;
    for (int t = 0; t < nch; t++) {
        const int kc = t * 32;
#pragma unroll
        for (int i = 0; i < 4; i++) {
            int c = wc0 + i * 4;
            float4 v = *reinterpret_cast<const float4*>(
                &Wbh[(size_t)(q0 + wr) * S_ + kc + c]);
            split4(v, &sW[0][wr * SPAD + c], &sW[1][wr * SPAD + c]);
        }
        {
            uint32_t hp[4], lp[4];
#pragma unroll
            for (int i = 0; i < 4; i++) {
                float x0 = g_qkv[vbase + (size_t)(kc + vk0 + 2 * i) * QKV_N + vd];
                float x1 = g_qkv[vbase + (size_t)(kc + vk0 + 2 * i + 1) * QKV_N + vd];
                __nv_bfloat162 hh, ll;
                hh.x = __float2bfloat16(x0); hh.y = __float2bfloat16(x1);
                ll.x = __float2bfloat16(x0 - __bfloat162float(hh.x));
                ll.y = __float2bfloat16(x1 - __bfloat162float(hh.y));
                hp[i] = *reinterpret_cast<uint32_t*>(&hh);
                lp[i] = *reinterpret_cast<uint32_t*>(&ll);
            }
            uint4 hv; hv.x = hp[0]; hv.y = hp[1]; hv.z = hp[2]; hv.w = hp[3];
            uint4 lv; lv.x = lp[0]; lv.y = lp[1]; lv.z = lp[2]; lv.w = lp[3];
            *reinterpret_cast<uint4*>(&sV[0][vd * SPAD + vk0]) = hv;
            *reinterpret_cast<uint4*>(&sV[1][vd * SPAD + vk0]) = lv;
        }
        __syncthreads();

#pragma unroll
        for (int ks = 0; ks < 32; ks += 16) {
            uint32_t a_h[4], a_l[4];
            uint32_t b_h[8][2], b_l[8][2];
            {
                int el = a_r * SPAD + ks + a_c;
                ldm_x4(a_h, smem_u32(&sW[0][el]));
                ldm_x4(a_l, smem_u32(&sW[1][el]));
            }
#pragma unroll
            for (int jj = 0; jj < 4; jj++) {
                int el = (b_r + jj * 16) * SPAD + ks + b_c;
                ldm_x4(&b_h[jj * 2][0], smem_u32(&sV[0][el]));
                ldm_x4(&b_l[jj * 2][0], smem_u32(&sV[1][el]));
            }
#pragma unroll
            for (int j = 0; j < 8; j++)
                mma_bf16(acc[j], a_h, b_h[j]);
#pragma unroll
            for (int j = 0; j < 8; j++)
                mma_bf16(acc[j], a_h, b_l[j]);
#pragma unroll
            for (int j = 0; j < 8; j++)
                mma_bf16(acc[j], a_l, b_h[j]);
        }
        __syncthreads();
    }

    // epilogue: split to bf16 hi/lo and write g_ahi/g_alo directly
#pragma unroll
    for (int j = 0; j < 8; j++) {
        int m = q0 + warp_m + (lane >> 2);
        int n = j * 8 + (lane & 3) * 2;
        size_t o0 = (size_t)(b * S_ + m) * D_ + h * DH_ + n;
        size_t o1 = (size_t)(b * S_ + m + 8) * D_ + h * DH_ + n;
        __nv_bfloat162 h0, l0, h1, l1;
        h0.x = __float2bfloat16(acc[j][0]);
        h0.y = __float2bfloat16(acc[j][1]);
        l0.x = __float2bfloat16(acc[j][0] - __bfloat162float(h0.x));
        l0.y = __float2bfloat16(acc[j][1] - __bfloat162float(h0.y));
        h1.x = __float2bfloat16(acc[j][2]);
        h1.y = __float2bfloat16(acc[j][3]);
        l1.x = __float2bfloat16(acc[j][2] - __bfloat162float(h1.x));
        l1.y = __float2bfloat16(acc[j][3] - __bfloat162float(h1.y));
        *reinterpret_cast<__nv_bfloat162*>(&g_ahi[o0]) = h0;
        *reinterpret_cast<__nv_bfloat162*>(&g_alo[o0]) = l0;
        *reinterpret_cast<__nv_bfloat162*>(&g_ahi[o1]) = h1;
        *reinterpret_cast<__nv_bfloat162*>(&g_alo[o1]) = l1;
    }
}

// ---------------------------------------------------------------------------
extern "C" void kernel_launch(void* const* d_in, const int* in_sizes, int n_in,
                              void* d_out, int out_size)
{
    const float* hs       = (const float*)d_in[0];
    const float* c_attn_w = (const float*)d_in[1];
    const float* c_attn_b = (const float*)d_in[2];
    const float* c_proj_w = (const float*)d_in[3];
    const float* c_proj_b = (const float*)d_in[4];

    float* out  = (float*)d_out;
    float* Wout = out + OUT_ATTN_ELEMS;

    float *qkv_ptr = nullptr;
    __nv_bfloat16 *ahi, *alo, *w1hi, *w1lo, *w2hi, *w2lo;
    cudaGetSymbolAddress((void**)&qkv_ptr, g_qkv);
    cudaGetSymbolAddress((void**)&ahi,  g_ahi);
    cudaGetSymbolAddress((void**)&alo,  g_alo);
    cudaGetSymbolAddress((void**)&w1hi, g_w1hi);
    cudaGetSymbolAddress((void**)&w1lo, g_w1lo);
    cudaGetSymbolAddress((void**)&w2hi, g_w2hi);
    cudaGetSymbolAddress((void**)&w2lo, g_w2lo);

    static bool attr_set = false;
    if (!attr_set) {
        cudaFuncSetAttribute(gemm_hmma_async,
                             cudaFuncAttributeMaxDynamicSharedMemorySize,
                             GEMM_SMEM_BYTES);
        attr_set = true;
    }

    // 0) splits for dense GEMMs
    split_rows_kernel<<<(BS_ * D_ / 4 + 255) / 256, 256>>>(hs, ahi, alo, BS_ * D_ / 4);
    split_T_kernel<<<dim3(QKV_N / 32, D_ / 32), 256>>>(c_attn_w, w1hi, w1lo, D_, QKV_N);
    split_T_kernel<<<dim3(D_ / 32, D_ / 32), 256>>>(c_proj_w, w2hi, w2lo, D_, D_);

    // 1) QKV GEMM (HMMA, cp.async pipelined)
    gemm_hmma_async<<<dim3(QKV_N / 128, BS_ / 128), 256, GEMM_SMEM_BYTES>>>(
        ahi, alo, w1hi, w1lo, c_attn_b, qkv_ptr, BS_, QKV_N, D_);

    // 2) Scores (HMMA, lower-triangle tiles only)
    scores_hmma_kernel<<<dim3(136, B_ * H_), 256>>>(Wout);

    // 3) Softmax in place (masked-region reads skipped)
    softmax_kernel<<<B_ * H_ * S_, 256>>>(Wout);

    // 4) AV (HMMA) -> writes g_ahi/g_alo directly (no fp32 pass)
    av_hmma_kernel<<<dim3(S_ / 128, B_ * H_), 256>>>(Wout);

    // 5) proj GEMM (HMMA, pipelined) — consumes g_ahi/g_alo from AV
    gemm_hmma_async<<<dim3(D_ / 128, BS_ / 128), 256, GEMM_SMEM_BYTES>>>(
        ahi, alo, w2hi, w2lo, c_proj_b, out, BS_, D_, D_);
}

// round 9
// speedup vs baseline: 1.5010x; 1.3312x over previous
#include <cuda_runtime.h>
#include <cuda_fp16.h>
#include <cstdint>
#include <cstddef>

// Problem constants
#define B_   2
#define S_   2048
#define D_   1024
#define H_   16
#define DH_  64
#define BS_  (B_ * S_)            // 4096
#define QKV_N (3 * D_)            // 3072
#define OUT_ATTN_ELEMS ((size_t)BS_ * D_)           // 4,194,304
#define MASKED_BIAS -10000.0f

// Scratch (allocation-free rule: __device__ globals)
__device__ float g_qkv[BS_ * QKV_N];   // [4096, 3072] : Q | K | V packed (fp32)
// fp16 split operands for the dense GEMMs
__device__ __half g_ahi[BS_ * D_];
__device__ __half g_alo[BS_ * D_];
__device__ __half g_w1h[QKV_N * D_];   // c_attn_w^T [3072,1024] fp16
__device__ __half g_w2h[D_ * D_];      // c_proj_w^T [1024,1024] fp16

// ===========================================================================
// HMMA / async-copy helpers
// ===========================================================================
__device__ __forceinline__ uint32_t smem_u32(const void* p) {
    uint32_t a;
    asm("{ .reg .u64 t; cvta.to.shared.u64 t, %1; cvt.u32.u64 %0, t; }"
        : "=r"(a) : "l"(p));
    return a;
}

__device__ __forceinline__ void ldm_x4(uint32_t r[4], uint32_t saddr) {
    asm volatile("ldmatrix.sync.aligned.m8n8.x4.shared.b16 {%0,%1,%2,%3}, [%4];"
                 : "=r"(r[0]), "=r"(r[1]), "=r"(r[2]), "=r"(r[3]) : "r"(saddr));
}

__device__ __forceinline__ void mma_f16(float c[4], const uint32_t a[4],
                                        const uint32_t b[2]) {
    asm volatile(
        "mma.sync.aligned.m16n8k16.row.col.f32.f16.f16.f32 "
        "{%0,%1,%2,%3}, {%4,%5,%6,%7}, {%8,%9}, {%0,%1,%2,%3};"
        : "+f"(c[0]), "+f"(c[1]), "+f"(c[2]), "+f"(c[3])
        : "r"(a[0]), "r"(a[1]), "r"(a[2]), "r"(a[3]), "r"(b[0]), "r"(b[1]));
}

__device__ __forceinline__ void cp16(uint32_t saddr, const void* gaddr) {
    asm volatile("cp.async.ca.shared.global [%0], [%1], 16;"
                 :: "r"(saddr), "l"(gaddr));
}
#define CP_COMMIT() asm volatile("cp.async.commit_group;" ::: "memory")
#define CP_WAIT(N)  asm volatile("cp.async.wait_group %0;" :: "n"(N) : "memory")

// Split a float4 into fp16 hi/lo (8B each).
__device__ __forceinline__ void split4h(float4 v, __half* hp, __half* lp)
{
    __half2 h0, h1, l0, l1;
    h0.x = __float2half_rn(v.x); h0.y = __float2half_rn(v.y);
    h1.x = __float2half_rn(v.z); h1.y = __float2half_rn(v.w);
    l0.x = __float2half_rn(v.x - __half2float(h0.x));
    l0.y = __float2half_rn(v.y - __half2float(h0.y));
    l1.x = __float2half_rn(v.z - __half2float(h1.x));
    l1.y = __float2half_rn(v.w - __half2float(h1.y));
    uint2 hu, lu;
    hu.x = *reinterpret_cast<uint32_t*>(&h0);
    hu.y = *reinterpret_cast<uint32_t*>(&h1);
    lu.x = *reinterpret_cast<uint32_t*>(&l0);
    lu.y = *reinterpret_cast<uint32_t*>(&l1);
    *reinterpret_cast<uint2*>(hp) = hu;
    *reinterpret_cast<uint2*>(lp) = lu;
}

// Convert a float4 to 4 fp16 (single 8B store).
__device__ __forceinline__ void conv4h(float4 v, __half* p)
{
    __half2 h0, h1;
    h0.x = __float2half_rn(v.x); h0.y = __float2half_rn(v.y);
    h1.x = __float2half_rn(v.z); h1.y = __float2half_rn(v.w);
    uint2 hu;
    hu.x = *reinterpret_cast<uint32_t*>(&h0);
    hu.y = *reinterpret_cast<uint32_t*>(&h1);
    *reinterpret_cast<uint2*>(p) = hu;
}

// ===========================================================================
// Split kernels
// ===========================================================================
__global__ __launch_bounds__(256)
void split_rows_kernel(const float* __restrict__ in,
                       __half* __restrict__ hi,
                       __half* __restrict__ lo, int n4)
{
    int i = blockIdx.x * 256 + threadIdx.x;
    if (i >= n4) return;
    float4 v = reinterpret_cast<const float4*>(in)[i];
    split4h(v, hi + i * 4, lo + i * 4);
}

// Transpose + convert: in [K,N] fp32 -> out [N,K] fp16 (single precision copy)
__global__ __launch_bounds__(256)
void conv_T_kernel(const float* __restrict__ in,
                   __half* __restrict__ hi, int K, int N)
{
    __shared__ float t[32][33];
    int n0 = blockIdx.x * 32, k0 = blockIdx.y * 32;
    int tx = threadIdx.x & 31, ty = threadIdx.x >> 5;   // 32 x 8
#pragma unroll
    for (int i = 0; i < 4; i++)
        t[ty + 8 * i][tx] = in[(size_t)(k0 + ty + 8 * i) * N + n0 + tx];
    __syncthreads();
#pragma unroll
    for (int i = 0; i < 4; i++) {
        float v = t[tx][ty + 8 * i];
        hi[(size_t)(n0 + ty + 8 * i) * K + k0 + tx] = __float2half_rn(v);
    }
}

// ===========================================================================
// cp.async double-buffered HMMA GEMM (fp16, 2-pass):
// C[M,N] = (Ahi+Alo)[M,K] @ B[N,K]^T + bias[N]
// 128x128 CTA tile, BK=32, 8 warps (4m x 2n), warp tile 32x64.
// ===========================================================================
#define SPAD    40
#define TILE_E  (128 * SPAD)
#define STAGE_E (3 * TILE_E)          // Ahi, Alo, B
#define GEMM_SMEM_BYTES (2 * STAGE_E * 2)

__device__ __forceinline__ void gemm_issue_loads(
    const __half* __restrict__ Ahi, const __half* __restrict__ Alo,
    const __half* __restrict__ B,
    uint32_t sm_base, int stage, int row0, int col0, int kk, int K, int tid)
{
    const uint32_t st = sm_base + (uint32_t)stage * STAGE_E * 2;
#pragma unroll
    for (int u = 0; u < 2; u++) {
        int s  = tid + u * 256;
        int r  = s >> 2;
        int cg = (s & 3) * 8;
        size_t goffA = (size_t)(row0 + r) * K + kk + cg;
        size_t goffB = (size_t)(col0 + r) * K + kk + cg;
        uint32_t so = (uint32_t)(r * SPAD + cg) * 2;
        cp16(st + 0 * TILE_E * 2 + so, Ahi + goffA);
        cp16(st + 1 * TILE_E * 2 + so, Alo + goffA);
        cp16(st + 2 * TILE_E * 2 + so, B + goffB);
    }
}

__global__ __launch_bounds__(256, 2)
void gemm_hmma_async(const __half* __restrict__ Ahi,
                     const __half* __restrict__ Alo,
                     const __half* __restrict__ B,
                     const float* __restrict__ bias,
                     float* __restrict__ C, int M, int N, int K)
{
    extern __shared__ __half sm[];
    const uint32_t sm_base = smem_u32(sm);

    const int tid  = threadIdx.x;
    const int lane = tid & 31;
    const int warp = tid >> 5;
    const int row0 = blockIdx.y * 128;
    const int col0 = blockIdx.x * 128;
    const int warp_m = (warp & 3) * 32;
    const int warp_n = (warp >> 2) * 64;

    float acc[2][8][4];
#pragma unroll
    for (int i = 0; i < 2; i++)
#pragma unroll
        for (int j = 0; j < 8; j++)
#pragma unroll
            for (int r = 0; r < 4; r++) acc[i][j][r] = 0.0f;

    const int a_r = warp_m + (lane & 15);
    const int a_c = (lane >> 4) * 8;
    const int b_r = warp_n + (lane & 7) + (lane >> 4) * 8;
    const int b_c = ((lane >> 3) & 1) * 8;

    const int nch = K >> 5;

    gemm_issue_loads(Ahi, Alo, B, sm_base, 0, row0, col0, 0, K, tid);
    CP_COMMIT();

    for (int c = 0; c < nch; c++) {
        const int cur = c & 1;
        if (c + 1 < nch) {
            gemm_issue_loads(Ahi, Alo, B, sm_base, cur ^ 1,
                             row0, col0, (c + 1) << 5, K, tid);
            CP_COMMIT();
            CP_WAIT(1);
        } else {
            CP_WAIT(0);
        }
        __syncthreads();

        const __half* sAhi = sm + cur * STAGE_E + 0 * TILE_E;
        const __half* sAlo = sm + cur * STAGE_E + 1 * TILE_E;
        const __half* sB   = sm + cur * STAGE_E + 2 * TILE_E;

#pragma unroll
        for (int ks = 0; ks < 32; ks += 16) {
            uint32_t a_h[2][4], a_l[2][4];
            uint32_t b_f[8][2];
#pragma unroll
            for (int i = 0; i < 2; i++) {
                int el = (a_r + i * 16) * SPAD + ks + a_c;
                ldm_x4(a_h[i], smem_u32(sAhi + el));
                ldm_x4(a_l[i], smem_u32(sAlo + el));
            }
#pragma unroll
            for (int jj = 0; jj < 4; jj++) {
                int el = (b_r + jj * 16) * SPAD + ks + b_c;
                ldm_x4(&b_f[jj * 2][0], smem_u32(sB + el));
            }
#pragma unroll
            for (int i = 0; i < 2; i++)
#pragma unroll
                for (int j = 0; j < 8; j++)
                    mma_f16(acc[i][j], a_h[i], b_f[j]);
#pragma unroll
            for (int i = 0; i < 2; i++)
#pragma unroll
                for (int j = 0; j < 8; j++)
                    mma_f16(acc[i][j], a_l[i], b_f[j]);
        }
        __syncthreads();
    }

#pragma unroll
    for (int i = 0; i < 2; i++) {
#pragma unroll
        for (int j = 0; j < 8; j++) {
            int m = row0 + warp_m + i * 16 + (lane >> 2);
            int n = col0 + warp_n + j * 8 + (lane & 3) * 2;
            float2 bz = *reinterpret_cast<const float2*>(&bias[n]);
            float2 o0; o0.x = acc[i][j][0] + bz.x; o0.y = acc[i][j][1] + bz.y;
            float2 o1; o1.x = acc[i][j][2] + bz.x; o1.y = acc[i][j][3] + bz.y;
            *reinterpret_cast<float2*>(&C[(size_t)m * N + n]) = o0;
            *reinterpret_cast<float2*>(&C[(size_t)(m + 8) * N + n]) = o1;
        }
    }
}

// ===========================================================================
// Scores on HMMA (fp16 2-pass): W[bh,q,k] = (Q.K)/8, masked.
// Q split hi/lo; K single fp16. Lower-triangle tiles only.
// ===========================================================================
__global__ __launch_bounds__(256)
void scores_hmma_kernel(float* __restrict__ W)
{
    __shared__ __half sQh[128 * SPAD];
    __shared__ __half sQl[128 * SPAD];
    __shared__ __half sKh[128 * SPAD];

    const int tid  = threadIdx.x;
    const int lane = tid & 31;
    const int warp = tid >> 5;
    const int bh   = blockIdx.y;
    const int b    = bh >> 4;
    const int h    = bh & 15;

    int pair = blockIdx.x;
    int qt = (int)((-1.0f + sqrtf(1.0f + 8.0f * (float)pair)) * 0.5f);
    while ((qt + 1) * (qt + 2) / 2 <= pair) ++qt;
    while (qt * (qt + 1) / 2 > pair) --qt;
    const int kt = pair - qt * (qt + 1) / 2;

    const int q0 = qt * 128;
    const int k0 = kt * 128;
    const int warp_m = (warp & 3) * 32;
    const int warp_n = (warp >> 2) * 64;

    float acc[2][8][4];
#pragma unroll
    for (int i = 0; i < 2; i++)
#pragma unroll
        for (int j = 0; j < 8; j++)
#pragma unroll
            for (int r = 0; r < 4; r++) acc[i][j][r] = 0.0f;

    const int a_r = warp_m + (lane & 15);
    const int a_c = (lane >> 4) * 8;
    const int b_r = warp_n + (lane & 7) + (lane >> 4) * 8;
    const int b_c = ((lane >> 3) & 1) * 8;

    const size_t qbase = (size_t)(b * S_ + q0) * QKV_N + h * DH_;
    const size_t kbase = (size_t)(b * S_ + k0) * QKV_N + D_ + h * DH_;

    const int lr = tid >> 1;
    const int lc0 = (tid & 1) * 16;

    for (int dc = 0; dc < DH_; dc += 32) {
#pragma unroll
        for (int i = 0; i < 4; i++) {
            int c = lc0 + i * 4;
            float4 vq = *reinterpret_cast<const float4*>(
                &g_qkv[qbase + (size_t)lr * QKV_N + dc + c]);
            float4 vk = *reinterpret_cast<const float4*>(
                &g_qkv[kbase + (size_t)lr * QKV_N + dc + c]);
            split4h(vq, &sQh[lr * SPAD + c], &sQl[lr * SPAD + c]);
            conv4h(vk, &sKh[lr * SPAD + c]);
        }
        __syncthreads();

#pragma unroll
        for (int ks = 0; ks < 32; ks += 16) {
            uint32_t a_h[2][4], a_l[2][4];
            uint32_t b_f[8][2];
#pragma unroll
            for (int i = 0; i < 2; i++) {
                int el = (a_r + i * 16) * SPAD + ks + a_c;
                ldm_x4(a_h[i], smem_u32(&sQh[el]));
                ldm_x4(a_l[i], smem_u32(&sQl[el]));
            }
#pragma unroll
            for (int jj = 0; jj < 4; jj++) {
                int el = (b_r + jj * 16) * SPAD + ks + b_c;
                ldm_x4(&b_f[jj * 2][0], smem_u32(&sKh[el]));
            }
#pragma unroll
            for (int i = 0; i < 2; i++)
#pragma unroll
                for (int j = 0; j < 8; j++)
                    mma_f16(acc[i][j], a_h[i], b_f[j]);
#pragma unroll
            for (int i = 0; i < 2; i++)
#pragma unroll
                for (int j = 0; j < 8; j++)
                    mma_f16(acc[i][j], a_l[i], b_f[j]);
        }
        __syncthreads();
    }

    float* Wbh = W + (size_t)bh * S_ * S_;
#pragma unroll
    for (int i = 0; i < 2; i++) {
#pragma unroll
        for (int j = 0; j < 8; j++) {
            int q  = q0 + warp_m + i * 16 + (lane >> 2);
            int k  = k0 + warp_n + j * 8 + (lane & 3) * 2;
            float2 o0, o1;
            o0.x = (k     > q) ? MASKED_BIAS : acc[i][j][0] * 0.125f;
            o0.y = (k + 1 > q) ? MASKED_BIAS : acc[i][j][1] * 0.125f;
            o1.x = (k     > q + 8) ? MASKED_BIAS : acc[i][j][2] * 0.125f;
            o1.y = (k + 1 > q + 8) ? MASKED_BIAS : acc[i][j][3] * 0.125f;
            *reinterpret_cast<float2*>(&Wbh[(size_t)q * S_ + k]) = o0;
            *reinterpret_cast<float2*>(&Wbh[(size_t)(q + 8) * S_ + k]) = o1;
        }
    }
}

// ---------------------------------------------------------------------------
// Softmax in place: float4 IO, warp-shuffle reductions, __expf.
// Masked-region float4 loads skipped.
// ---------------------------------------------------------------------------
__global__ __launch_bounds__(256)
void softmax_kernel(float* __restrict__ W)
{
    const int tid = threadIdx.x;
    const int lane = tid & 31;
    const int warp = tid >> 5;
    const int row = blockIdx.x;
    const int q = row & (S_ - 1);
    const int nvalid = q + 1;
    float* w = W + (size_t)row * S_;

    __shared__ float red[8];

    float4 v[2];
    float m = -1e30f;
#pragma unroll
    for (int r = 0; r < 2; r++) {
        int k0 = (r * 256 + tid) * 4;
        float4 x;
        if (k0 < nvalid) {
            x = *reinterpret_cast<const float4*>(w + k0);
            x.x = (k0 + 0 < nvalid) ? x.x : -1e30f;
            x.y = (k0 + 1 < nvalid) ? x.y : -1e30f;
            x.z = (k0 + 2 < nvalid) ? x.z : -1e30f;
            x.w = (k0 + 3 < nvalid) ? x.w : -1e30f;
        } else {
            x.x = x.y = x.z = x.w = -1e30f;
        }
        v[r] = x;
        m = fmaxf(m, fmaxf(fmaxf(x.x, x.y), fmaxf(x.z, x.w)));
    }
#pragma unroll
    for (int off = 16; off > 0; off >>= 1)
        m = fmaxf(m, __shfl_xor_sync(0xFFFFFFFFu, m, off));
    if (lane == 0) red[warp] = m;
    __syncthreads();
    float mx = red[0];
#pragma unroll
    for (int i = 1; i < 8; i++) mx = fmaxf(mx, red[i]);
    __syncthreads();

    float s = 0.0f;
#pragma unroll
    for (int r = 0; r < 2; r++) {
        int k0 = (r * 256 + tid) * 4;
        float4 x = v[r];
        x.x = (k0 + 0 < nvalid) ? __expf(x.x - mx) : 0.0f;
        x.y = (k0 + 1 < nvalid) ? __expf(x.y - mx) : 0.0f;
        x.z = (k0 + 2 < nvalid) ? __expf(x.z - mx) : 0.0f;
        x.w = (k0 + 3 < nvalid) ? __expf(x.w - mx) : 0.0f;
        v[r] = x;
        s += x.x + x.y + x.z + x.w;
    }
#pragma unroll
    for (int off = 16; off > 0; off >>= 1)
        s += __shfl_xor_sync(0xFFFFFFFFu, s, off);
    if (lane == 0) red[warp] = s;
    __syncthreads();
    float tot = red[0];
#pragma unroll
    for (int i = 1; i < 8; i++) tot += red[i];
    const float inv = 1.0f / tot;

#pragma unroll
    for (int r = 0; r < 2; r++) {
        int k0 = (r * 256 + tid) * 4;
        float4 x = v[r];
        x.x *= inv; x.y *= inv; x.z *= inv; x.w *= inv;
        *reinterpret_cast<float4*>(w + k0) = x;
    }
}

// ===========================================================================
// AV on HMMA (fp16 2-pass): attn = softmax(W) @ V, causal chunk range.
// W split hi/lo; V single fp16. Epilogue writes fp16 hi/lo into g_ahi/g_alo.
// ===========================================================================
__global__ __launch_bounds__(256)
void av_hmma_kernel(const float* __restrict__ W)
{
    __shared__ __half sWh[128 * SPAD];
    __shared__ __half sWl[128 * SPAD];
    __shared__ __half sVh[64 * SPAD];

    const int tid  = threadIdx.x;
    const int lane = tid & 31;
    const int warp = tid >> 5;
    const int bh   = blockIdx.y;
    const int b    = bh >> 4;
    const int h    = bh & 15;
    const int q0   = blockIdx.x * 128;
    const int warp_m = warp * 16;

    const float* Wbh = W + (size_t)bh * S_ * S_;
    const size_t vbase = (size_t)b * S_ * QKV_N + 2 * D_ + h * DH_;

    float acc[8][4];
#pragma unroll
    for (int j = 0; j < 8; j++)
#pragma unroll
        for (int r = 0; r < 4; r++) acc[j][r] = 0.0f;

    const int a_r = warp_m + (lane & 15);
    const int a_c = (lane >> 4) * 8;
    const int b_r = (lane & 7) + (lane >> 4) * 8;
    const int b_c = ((lane >> 3) & 1) * 8;

    const int wr  = tid >> 1;
    const int wc0 = (tid & 1) * 16;
    const int vd  = tid & 63;
    const int vk0 = (tid >> 6) * 8;

    const int nch = (blockIdx.x + 1) * 4;
    for (int t = 0; t < nch; t++) {
        const int kc = t * 32;
#pragma unroll
        for (int i = 0; i < 4; i++) {
            int c = wc0 + i * 4;
            float4 v = *reinterpret_cast<const float4*>(
                &Wbh[(size_t)(q0 + wr) * S_ + kc + c]);
            split4h(v, &sWh[wr * SPAD + c], &sWl[wr * SPAD + c]);
        }
        {
            uint32_t hp[4];
#pragma unroll
            for (int i = 0; i < 4; i++) {
                float x0 = g_qkv[vbase + (size_t)(kc + vk0 + 2 * i) * QKV_N + vd];
                float x1 = g_qkv[vbase + (size_t)(kc + vk0 + 2 * i + 1) * QKV_N + vd];
                __half2 hh;
                hh.x = __float2half_rn(x0); hh.y = __float2half_rn(x1);
                hp[i] = *reinterpret_cast<uint32_t*>(&hh);
            }
            uint4 hv; hv.x = hp[0]; hv.y = hp[1]; hv.z = hp[2]; hv.w = hp[3];
            *reinterpret_cast<uint4*>(&sVh[vd * SPAD + vk0]) = hv;
        }
        __syncthreads();

#pragma unroll
        for (int ks = 0; ks < 32; ks += 16) {
            uint32_t a_h[4], a_l[4];
            uint32_t b_f[8][2];
            {
                int el = a_r * SPAD + ks + a_c;
                ldm_x4(a_h, smem_u32(&sWh[el]));
                ldm_x4(a_l, smem_u32(&sWl[el]));
            }
#pragma unroll
            for (int jj = 0; jj < 4; jj++) {
                int el = (b_r + jj * 16) * SPAD + ks + b_c;
                ldm_x4(&b_f[jj * 2][0], smem_u32(&sVh[el]));
            }
#pragma unroll
            for (int j = 0; j < 8; j++)
                mma_f16(acc[j], a_h, b_f[j]);
#pragma unroll
            for (int j = 0; j < 8; j++)
                mma_f16(acc[j], a_l, b_f[j]);
        }
        __syncthreads();
    }

    // epilogue: split to fp16 hi/lo and write g_ahi/g_alo directly
#pragma unroll
    for (int j = 0; j < 8; j++) {
        int m = q0 + warp_m + (lane >> 2);
        int n = j * 8 + (lane & 3) * 2;
        size_t o0 = (size_t)(b * S_ + m) * D_ + h * DH_ + n;
        size_t o1 = (size_t)(b * S_ + m + 8) * D_ + h * DH_ + n;
        __half2 h0, l0, h1, l1;
        h0.x = __float2half_rn(acc[j][0]);
        h0.y = __float2half_rn(acc[j][1]);
        l0.x = __float2half_rn(acc[j][0] - __half2float(h0.x));
        l0.y = __float2half_rn(acc[j][1] - __half2float(h0.y));
        h1.x = __float2half_rn(acc[j][2]);
        h1.y = __float2half_rn(acc[j][3]);
        l1.x = __float2half_rn(acc[j][2] - __half2float(h1.x));
        l1.y = __float2half_rn(acc[j][3] - __half2float(h1.y));
        *reinterpret_cast<__half2*>(&g_ahi[o0]) = h0;
        *reinterpret_cast<__half2*>(&g_alo[o0]) = l0;
        *reinterpret_cast<__half2*>(&g_ahi[o1]) = h1;
        *reinterpret_cast<__half2*>(&g_alo[o1]) = l1;
    }
}

// ---------------------------------------------------------------------------
extern "C" void kernel_launch(void* const* d_in, const int* in_sizes, int n_in,
                              void* d_out, int out_size)
{
    const float* hs       = (const float*)d_in[0];
    const float* c_attn_w = (const float*)d_in[1];
    const float* c_attn_b = (const float*)d_in[2];
    const float* c_proj_w = (const float*)d_in[3];
    const float* c_proj_b = (const float*)d_in[4];

    float* out  = (float*)d_out;
    float* Wout = out + OUT_ATTN_ELEMS;

    float *qkv_ptr = nullptr;
    __half *ahi, *alo, *w1h, *w2h;
    cudaGetSymbolAddress((void**)&qkv_ptr, g_qkv);
    cudaGetSymbolAddress((void**)&ahi, g_ahi);
    cudaGetSymbolAddress((void**)&alo, g_alo);
    cudaGetSymbolAddress((void**)&w1h, g_w1h);
    cudaGetSymbolAddress((void**)&w2h, g_w2h);

    static bool attr_set = false;
    if (!attr_set) {
        cudaFuncSetAttribute(gemm_hmma_async,
                             cudaFuncAttributeMaxDynamicSharedMemorySize,
                             GEMM_SMEM_BYTES);
        attr_set = true;
    }

    // 0) splits/conversions for dense GEMMs
    split_rows_kernel<<<(BS_ * D_ / 4 + 255) / 256, 256>>>(hs, ahi, alo, BS_ * D_ / 4);
    conv_T_kernel<<<dim3(QKV_N / 32, D_ / 32), 256>>>(c_attn_w, w1h, D_, QKV_N);
    conv_T_kernel<<<dim3(D_ / 32, D_ / 32), 256>>>(c_proj_w, w2h, D_, D_);

    // 1) QKV GEMM (HMMA fp16 2-pass, cp.async pipelined)
    gemm_hmma_async<<<dim3(QKV_N / 128, BS_ / 128), 256, GEMM_SMEM_BYTES>>>(
        ahi, alo, w1h, c_attn_b, qkv_ptr, BS_, QKV_N, D_);

    // 2) Scores (HMMA fp16 2-pass, lower-triangle tiles only)
    scores_hmma_kernel<<<dim3(136, B_ * H_), 256>>>(Wout);

    // 3) Softmax in place (masked-region reads skipped)
    softmax_kernel<<<B_ * H_ * S_, 256>>>(Wout);

    // 4) AV (HMMA fp16 2-pass) -> writes g_ahi/g_alo directly
    av_hmma_kernel<<<dim3(S_ / 128, B_ * H_), 256>>>(Wout);

    // 5) proj GEMM (HMMA fp16 2-pass) — consumes g_ahi/g_alo from AV
    gemm_hmma_async<<<dim3(D_ / 128, BS_ / 128), 256, GEMM_SMEM_BYTES>>>(
        ahi, alo, w2h, c_proj_b, out, BS_, D_, D_);
}